// round 1
// baseline (speedup 1.0000x reference)
#include <cuda_runtime.h>
#include <math.h>

// Problem constants
#define BATCH 4
#define SEQ   2048
#define T     8192      // BATCH*SEQ tokens
#define H     1024
#define E     8
#define F     2048

// GEMM tiling
#define BM 64
#define BN 64
#define BK 16

// -------- scratch (static device globals; no allocation) --------
__device__ float g_Hact[(size_t)E * T * F];   // silu(x@w1+b1), per (expert,slot)
__device__ float g_Yout[(size_t)E * T * H];   // h@w2, per (expert,slot)
__device__ int   g_tok[E * T];                // token ids per expert list
__device__ int   g_cnt[E];                    // per-expert routed count
__device__ int   g_pair[T * 2];               // token -> pair index (e*T+pos)
__device__ int   g_pexp[T * 2];               // token -> expert id
__device__ float g_loss[2];                   // raw aux sum, raw z sum

// -------- init --------
__global__ void k_init() {
    int i = threadIdx.x;
    if (i < E) g_cnt[i] = 0;
    if (i < 2) g_loss[i] = 0.0f;
}

// -------- router: one warp per token --------
__global__ void k_router(const float* __restrict__ x,
                         const float* __restrict__ rw) {
    __shared__ float sw[E * H];  // 32 KB
    for (int i = threadIdx.x; i < E * H; i += blockDim.x) sw[i] = rw[i];
    __syncthreads();

    int lane = threadIdx.x & 31;
    int warp = threadIdx.x >> 5;
    int t = blockIdx.x * (blockDim.x >> 5) + warp;
    if (t >= T) return;

    float xr[32];
    const float* xp = x + (size_t)t * H;
#pragma unroll
    for (int i = 0; i < 32; i++) xr[i] = xp[lane + 32 * i];

    float lg[E];
#pragma unroll
    for (int e = 0; e < E; e++) {
        const float* w = sw + e * H;
        float s = 0.0f;
#pragma unroll
        for (int i = 0; i < 32; i++) s += xr[i] * w[lane + 32 * i];
#pragma unroll
        for (int o = 16; o > 0; o >>= 1) s += __shfl_xor_sync(0xffffffffu, s, o);
        lg[e] = s;
    }

    if (lane == 0) {
        float m = lg[0];
#pragma unroll
        for (int e = 1; e < E; e++) m = fmaxf(m, lg[e]);
        float se = 0.0f, sl = 0.0f, z = 0.0f;
#pragma unroll
        for (int e = 0; e < E; e++) {
            se += expf(lg[e] - m);
            sl += lg[e];
            z  += lg[e] * lg[e];
        }
        float lse = m + logf(se);
        float sumlogp = sl - (float)E * lse;
        // sum_e (1/E)*(log(1/E) - logp) for this token:
        float aux = -2.0794415416798357f - sumlogp * (1.0f / (float)E);
        atomicAdd(&g_loss[0], aux);
        atomicAdd(&g_loss[1], z);

        // top-2
        int e0 = 0;
#pragma unroll
        for (int e = 1; e < E; e++) if (lg[e] > lg[e0]) e0 = e;
        int e1 = (e0 == 0) ? 1 : 0;
#pragma unroll
        for (int e = 0; e < E; e++)
            if (e != e0 && lg[e] > lg[e1]) e1 = e;

        int es[2] = {e0, e1};
#pragma unroll
        for (int k = 0; k < 2; k++) {
            int e = es[k];
            int pos = atomicAdd(&g_cnt[e], 1);
            g_tok[e * T + pos]  = t;
            g_pair[t * 2 + k]   = e * T + pos;
            g_pexp[t * 2 + k]   = e;
        }
    }
}

// -------- GEMM1: Hact = silu( gather(x) @ w1[e] + b1[e] ) --------
// grid: (F/BN, T/BM, E), block 256 (16x16), each thread 4x4 outputs.
__global__ void k_gemm1(const float* __restrict__ x,
                        const float* __restrict__ w1,
                        const float* __restrict__ b1) {
    int e  = blockIdx.z;
    int ne = g_cnt[e];
    int gm = blockIdx.y * BM;
    if (gm >= ne) return;
    int gn = blockIdx.x * BN;

    __shared__ float As[BK][BM + 1];
    __shared__ float Bs[BK][BN];
    __shared__ int   stok[BM];

    int tid = threadIdx.x;
    int tx = tid & 15;
    int ty = tid >> 4;

    if (tid < BM) {
        int r = gm + tid;
        stok[tid] = (r < ne) ? g_tok[e * T + r] : -1;
    }
    __syncthreads();

    float acc[4][4];
#pragma unroll
    for (int i = 0; i < 4; i++)
#pragma unroll
        for (int j = 0; j < 4; j++) acc[i][j] = 0.0f;

    for (int k0 = 0; k0 < H; k0 += BK) {
        // load A (gathered rows of x): 64x16
#pragma unroll
        for (int i = tid; i < BM * BK; i += 256) {
            int r = i >> 4;
            int k = i & 15;
            int tk = stok[r];
            As[k][r] = (tk >= 0) ? x[(size_t)tk * H + k0 + k] : 0.0f;
        }
        // load B (w1[e] panel): 16x64
#pragma unroll
        for (int i = tid; i < BK * BN; i += 256) {
            int k = i >> 6;
            int n = i & 63;
            Bs[k][n] = w1[((size_t)e * H + (k0 + k)) * F + gn + n];
        }
        __syncthreads();

#pragma unroll
        for (int k = 0; k < BK; k++) {
            float a[4], b[4];
#pragma unroll
            for (int i = 0; i < 4; i++) a[i] = As[k][ty * 4 + i];
#pragma unroll
            for (int j = 0; j < 4; j++) b[j] = Bs[k][tx * 4 + j];
#pragma unroll
            for (int i = 0; i < 4; i++)
#pragma unroll
                for (int j = 0; j < 4; j++) acc[i][j] += a[i] * b[j];
        }
        __syncthreads();
    }

    // epilogue: + b1, silu, store
#pragma unroll
    for (int i = 0; i < 4; i++) {
        int row = ty * 4 + i;
        if (gm + row >= ne) continue;
        size_t base = ((size_t)(e * T + gm + row)) * F + gn;
#pragma unroll
        for (int j = 0; j < 4; j++) {
            int col = tx * 4 + j;
            float v = acc[i][j] + b1[e * F + gn + col];
            float s = v / (1.0f + expf(-v));
            g_Hact[base + col] = s;
        }
    }
}

// -------- GEMM2: Yout = Hact @ w2[e] --------
// grid: (H/BN, T/BM, E)
__global__ void k_gemm2(const float* __restrict__ w2) {
    int e  = blockIdx.z;
    int ne = g_cnt[e];
    int gm = blockIdx.y * BM;
    if (gm >= ne) return;
    int gn = blockIdx.x * BN;

    __shared__ float As[BK][BM + 1];
    __shared__ float Bs[BK][BN];

    int tid = threadIdx.x;
    int tx = tid & 15;
    int ty = tid >> 4;

    float acc[4][4];
#pragma unroll
    for (int i = 0; i < 4; i++)
#pragma unroll
        for (int j = 0; j < 4; j++) acc[i][j] = 0.0f;

    for (int k0 = 0; k0 < F; k0 += BK) {
#pragma unroll
        for (int i = tid; i < BM * BK; i += 256) {
            int r = i >> 4;
            int k = i & 15;
            As[k][r] = (gm + r < ne)
                ? g_Hact[((size_t)(e * T + gm + r)) * F + k0 + k]
                : 0.0f;
        }
#pragma unroll
        for (int i = tid; i < BK * BN; i += 256) {
            int k = i >> 6;
            int n = i & 63;
            Bs[k][n] = w2[((size_t)e * F + (k0 + k)) * H + gn + n];
        }
        __syncthreads();

#pragma unroll
        for (int k = 0; k < BK; k++) {
            float a[4], b[4];
#pragma unroll
            for (int i = 0; i < 4; i++) a[i] = As[k][ty * 4 + i];
#pragma unroll
            for (int j = 0; j < 4; j++) b[j] = Bs[k][tx * 4 + j];
#pragma unroll
            for (int i = 0; i < 4; i++)
#pragma unroll
                for (int j = 0; j < 4; j++) acc[i][j] += a[i] * b[j];
        }
        __syncthreads();
    }

#pragma unroll
    for (int i = 0; i < 4; i++) {
        int row = ty * 4 + i;
        if (gm + row >= ne) continue;
        size_t base = ((size_t)(e * T + gm + row)) * H + gn;
#pragma unroll
        for (int j = 0; j < 4; j++) {
            g_Yout[base + tx * 4 + j] = acc[i][j];
        }
    }
}

// -------- combine: out[t] = Y[p0] + Y[p1] + b2[e0] + b2[e1] --------
__global__ void k_combine(const float* __restrict__ b2,
                          float* __restrict__ out) {
    int t = blockIdx.x;
    int p0 = g_pair[2 * t], p1 = g_pair[2 * t + 1];
    int e0 = g_pexp[2 * t], e1 = g_pexp[2 * t + 1];

    const float4* y0  = (const float4*)(g_Yout + (size_t)p0 * H);
    const float4* y1  = (const float4*)(g_Yout + (size_t)p1 * H);
    const float4* bb0 = (const float4*)(b2 + (size_t)e0 * H);
    const float4* bb1 = (const float4*)(b2 + (size_t)e1 * H);
    float4* o = (float4*)(out + (size_t)t * H);

    int i = threadIdx.x;  // 256 threads, H/4 = 256
    float4 a = y0[i], b = y1[i], c = bb0[i], d = bb1[i];
    o[i] = make_float4(a.x + b.x + c.x + d.x,
                       a.y + b.y + c.y + d.y,
                       a.z + b.z + c.z + d.z,
                       a.w + b.w + c.w + d.w);
}

// -------- finalize: router_loss scalar appended after the [T,H] tensor --------
__global__ void k_finalize(float* __restrict__ out, int out_size) {
    if (out_size > T * H) {
        float aux = g_loss[0] * (0.001f / (float)BATCH);
        float z   = g_loss[1] * (0.001f / (float)(T * E));
        out[T * H] = aux + z;
    }
}

extern "C" void kernel_launch(void* const* d_in, const int* in_sizes, int n_in,
                              void* d_out, int out_size) {
    const float* x  = (const float*)d_in[0];  // [4,2048,1024]
    const float* rw = (const float*)d_in[1];  // [8,1024]
    const float* w1 = (const float*)d_in[2];  // [8,1024,2048]
    const float* b1 = (const float*)d_in[3];  // [8,2048]
    const float* w2 = (const float*)d_in[4];  // [8,2048,1024]
    const float* b2 = (const float*)d_in[5];  // [8,1024]
    float* out = (float*)d_out;

    k_init<<<1, 32>>>();
    k_router<<<T / 8, 256>>>(x, rw);

    dim3 g1(F / BN, T / BM, E);   // (32,128,8)
    k_gemm1<<<g1, 256>>>(x, w1, b1);

    dim3 g2(H / BN, T / BM, E);   // (16,128,8)
    k_gemm2<<<g2, 256>>>(w2);

    k_combine<<<T, 256>>>(b2, out);
    k_finalize<<<1, 1>>>(out, out_size);
}

// round 3
// speedup vs baseline: 9.9498x; 9.9498x over previous
#include <cuda_runtime.h>
#include <cuda_fp16.h>
#include <math.h>
#include <stdint.h>

// ---------------- problem constants ----------------
#define BATCH 4
#define T     8192
#define H     1024
#define E     8
#define F     2048

// ---------------- GEMM tiling ----------------
#define MT 128
#define NT 128
#define KT 32
#define NSTG 3
#define A_STRIDE 40     // fp16 per A smem row (32 + 8 pad)
#define B_STRIDE 136    // fp16 per B smem row (128 + 8 pad)
#define A_STAGE_BYTES (MT * A_STRIDE * 2)   // 10240
#define B_STAGE_BYTES (KT * B_STRIDE * 2)   // 8704
#define STAGE_BYTES (A_STAGE_BYTES + B_STAGE_BYTES)
#define SMEM_DYN (NSTG * STAGE_BYTES)       // 56832

// ---------------- scratch (static device globals) ----------------
__device__ __half g_xh[(size_t)T * H];
__device__ __half g_w1h[(size_t)E * H * F];
__device__ __half g_w2h[(size_t)E * F * H];
__device__ __half g_Hact[(size_t)E * T * F];   // silu(x@w1+b1), fp16
__device__ float  g_Yout[(size_t)E * T * H];   // h@w2, fp32
__device__ int    g_tok[E * T];
__device__ int    g_cnt[E];
__device__ int    g_pair[T * 2];
__device__ int    g_pexp[T * 2];
__device__ float  g_loss[2];

// ---------------- PTX helpers (all sm_80+ / non-arch-specific) ----------------
__device__ __forceinline__ uint32_t smem_u32(const void* p) {
    uint32_t a;
    asm("{ .reg .u64 t; cvta.to.shared.u64 t, %1; cvt.u32.u64 %0, t; }"
        : "=r"(a) : "l"(p));
    return a;
}
__device__ __forceinline__ void cp_async16(uint32_t dst, const void* src, uint32_t src_size) {
    asm volatile("cp.async.cg.shared.global [%0], [%1], 16, %2;"
                 :: "r"(dst), "l"(src), "r"(src_size));
}
#define CP_COMMIT() asm volatile("cp.async.commit_group;")
#define CP_WAIT1()  asm volatile("cp.async.wait_group 1;")
#define CP_WAIT0()  asm volatile("cp.async.wait_group 0;")

__device__ __forceinline__ void ldsm_x4(uint32_t& r0, uint32_t& r1, uint32_t& r2, uint32_t& r3,
                                        uint32_t addr) {
    asm volatile("ldmatrix.sync.aligned.m8n8.x4.shared.b16 {%0,%1,%2,%3}, [%4];"
                 : "=r"(r0), "=r"(r1), "=r"(r2), "=r"(r3) : "r"(addr));
}
__device__ __forceinline__ void ldsm_x4_t(uint32_t& r0, uint32_t& r1, uint32_t& r2, uint32_t& r3,
                                          uint32_t addr) {
    asm volatile("ldmatrix.sync.aligned.m8n8.x4.trans.shared.b16 {%0,%1,%2,%3}, [%4];"
                 : "=r"(r0), "=r"(r1), "=r"(r2), "=r"(r3) : "r"(addr));
}
__device__ __forceinline__ void mma_f16(float* c, const uint32_t* a, uint32_t b0, uint32_t b1) {
    asm volatile("mma.sync.aligned.m16n8k16.row.col.f32.f16.f16.f32 "
                 "{%0,%1,%2,%3}, {%4,%5,%6,%7}, {%8,%9}, {%0,%1,%2,%3};"
                 : "+f"(c[0]), "+f"(c[1]), "+f"(c[2]), "+f"(c[3])
                 : "r"(a[0]), "r"(a[1]), "r"(a[2]), "r"(a[3]), "r"(b0), "r"(b1));
}

// ---------------- init ----------------
__global__ void k_init() {
    int i = threadIdx.x;
    if (i < E) g_cnt[i] = 0;
    if (i < 2) g_loss[i] = 0.0f;
}

// ---------------- fp32 -> fp16 convert ----------------
__global__ void k_cvt(const float4* __restrict__ src, __half2* __restrict__ dst, int n4) {
    int i = blockIdx.x * blockDim.x + threadIdx.x;
    if (i < n4) {
        float4 v = src[i];
        dst[2 * i]     = __floats2half2_rn(v.x, v.y);
        dst[2 * i + 1] = __floats2half2_rn(v.z, v.w);
    }
}

// ---------------- router: one warp per token ----------------
__global__ void k_router(const float* __restrict__ x,
                         const float* __restrict__ rw) {
    __shared__ float sw[E * H];
    for (int i = threadIdx.x; i < E * H; i += blockDim.x) sw[i] = rw[i];
    __syncthreads();

    int lane = threadIdx.x & 31;
    int warp = threadIdx.x >> 5;
    int t = blockIdx.x * (blockDim.x >> 5) + warp;
    if (t >= T) return;

    float xr[32];
    const float* xp = x + (size_t)t * H;
#pragma unroll
    for (int i = 0; i < 32; i++) xr[i] = xp[lane + 32 * i];

    float lg[E];
#pragma unroll
    for (int e = 0; e < E; e++) {
        const float* w = sw + e * H;
        float s = 0.0f;
#pragma unroll
        for (int i = 0; i < 32; i++) s += xr[i] * w[lane + 32 * i];
#pragma unroll
        for (int o = 16; o > 0; o >>= 1) s += __shfl_xor_sync(0xffffffffu, s, o);
        lg[e] = s;
    }

    if (lane == 0) {
        float m = lg[0];
#pragma unroll
        for (int e = 1; e < E; e++) m = fmaxf(m, lg[e]);
        float se = 0.0f, sl = 0.0f, z = 0.0f;
#pragma unroll
        for (int e = 0; e < E; e++) {
            se += expf(lg[e] - m); sl += lg[e]; z += lg[e] * lg[e];
        }
        float lse = m + logf(se);
        float sumlogp = sl - (float)E * lse;
        float aux = -2.0794415416798357f - sumlogp * (1.0f / (float)E);
        atomicAdd(&g_loss[0], aux);
        atomicAdd(&g_loss[1], z);

        int e0 = 0;
#pragma unroll
        for (int e = 1; e < E; e++) if (lg[e] > lg[e0]) e0 = e;
        int e1 = (e0 == 0) ? 1 : 0;
#pragma unroll
        for (int e = 0; e < E; e++)
            if (e != e0 && lg[e] > lg[e1]) e1 = e;

        int es[2] = {e0, e1};
#pragma unroll
        for (int k = 0; k < 2; k++) {
            int e = es[k];
            int pos = atomicAdd(&g_cnt[e], 1);
            g_tok[e * T + pos] = t;
            g_pair[t * 2 + k] = e * T + pos;
            g_pexp[t * 2 + k] = e;
        }
    }
}

// ---------------- GEMM1: Hact = silu( gather(xh) @ w1h[e] + b1[e] ) ----------------
// A: gathered rows of xh [MT][KT], B: w1h[e] is [H][F] = [k][n] row-major (ldmatrix.trans)
__global__ __launch_bounds__(256, 2) void k_gemm1(const float* __restrict__ b1) {
    extern __shared__ char smem[];
    __shared__ int stok[MT];

    int e = blockIdx.z;
    int ne = g_cnt[e];
    int gm = blockIdx.y * MT;
    if (gm >= ne) return;
    int gn = blockIdx.x * NT;

    int tid = threadIdx.x, lane = tid & 31, wid = tid >> 5;
    int wm = wid & 1, wn = wid >> 1;   // 2 x 4 warp grid; warp tile 64x32

    if (tid < MT) stok[tid] = (gm + tid < ne) ? g_tok[e * T + gm + tid] : -1;
    __syncthreads();

    const __half* wB = g_w1h + (size_t)e * H * F;
    uint32_t sbase = smem_u32(smem);

    float cfrag[4][4][4];
#pragma unroll
    for (int i = 0; i < 4; i++)
#pragma unroll
        for (int j = 0; j < 4; j++)
#pragma unroll
            for (int k = 0; k < 4; k++) cfrag[i][j][k] = 0.0f;

    const int k_iters = H / KT;  // 32

    // stage loader
    auto load_stage = [&](int buf, int k0) {
        uint32_t aB = sbase + buf * STAGE_BYTES;
        uint32_t bB = aB + A_STAGE_BYTES;
#pragma unroll
        for (int q = 0; q < 2; q++) {
            int g = tid + q * 256;
            int r = g >> 2, cg = g & 3;
            int tk = stok[r];
            const __half* src = g_xh + (size_t)(tk < 0 ? 0 : tk) * H + k0 + cg * 8;
            cp_async16(aB + r * (A_STRIDE * 2) + cg * 16, src, tk >= 0 ? 16u : 0u);
        }
#pragma unroll
        for (int q = 0; q < 2; q++) {
            int g = tid + q * 256;
            int r = g >> 4, cg = g & 15;
            const __half* src = wB + (size_t)(k0 + r) * F + gn + cg * 8;
            cp_async16(bB + r * (B_STRIDE * 2) + cg * 16, src, 16u);
        }
    };

    load_stage(0, 0); CP_COMMIT();
    load_stage(1, KT); CP_COMMIT();

    for (int it = 0; it < k_iters; it++) {
        CP_WAIT1();
        __syncthreads();
        if (it + 2 < k_iters) load_stage((it + 2) % NSTG, (it + 2) * KT);
        CP_COMMIT();

        uint32_t aS = sbase + (it % NSTG) * STAGE_BYTES;
        uint32_t bS = aS + A_STAGE_BYTES;
#pragma unroll
        for (int ks = 0; ks < 2; ks++) {
            uint32_t a[4][4], b[2][4];
#pragma unroll
            for (int mf = 0; mf < 4; mf++) {
                int m = wm * 64 + mf * 16 + (lane & 15);
                int k = ks * 16 + (lane >> 4) * 8;
                ldsm_x4(a[mf][0], a[mf][1], a[mf][2], a[mf][3],
                        aS + m * (A_STRIDE * 2) + k * 2);
            }
#pragma unroll
            for (int np = 0; np < 2; np++) {
                int k = ks * 16 + (lane & 7) + ((lane >> 3) & 1) * 8;
                int n = wn * 32 + np * 16 + (lane >> 4) * 8;
                ldsm_x4_t(b[np][0], b[np][1], b[np][2], b[np][3],
                          bS + k * (B_STRIDE * 2) + n * 2);
            }
#pragma unroll
            for (int mf = 0; mf < 4; mf++)
#pragma unroll
                for (int nf = 0; nf < 4; nf++)
                    mma_f16(cfrag[mf][nf], a[mf],
                            b[nf >> 1][(nf & 1) * 2], b[nf >> 1][(nf & 1) * 2 + 1]);
        }
    }
    CP_WAIT0();

    // epilogue: bias + silu + fp16 store
#pragma unroll
    for (int nf = 0; nf < 4; nf++) {
        int col = gn + wn * 32 + nf * 8 + (lane & 3) * 2;
        float bias0 = b1[e * F + col];
        float bias1 = b1[e * F + col + 1];
#pragma unroll
        for (int mf = 0; mf < 4; mf++) {
            int r0 = gm + wm * 64 + mf * 16 + (lane >> 2);
            float* c = cfrag[mf][nf];
            if (r0 < ne) {
                float v0 = c[0] + bias0, v1 = c[1] + bias1;
                v0 = v0 / (1.0f + expf(-v0));
                v1 = v1 / (1.0f + expf(-v1));
                *(__half2*)(g_Hact + ((size_t)e * T + r0) * F + col) =
                    __floats2half2_rn(v0, v1);
            }
            if (r0 + 8 < ne) {
                float v2 = c[2] + bias0, v3 = c[3] + bias1;
                v2 = v2 / (1.0f + expf(-v2));
                v3 = v3 / (1.0f + expf(-v3));
                *(__half2*)(g_Hact + ((size_t)e * T + r0 + 8) * F + col) =
                    __floats2half2_rn(v2, v3);
            }
        }
    }
}

// ---------------- GEMM2: Yout = Hact @ w2h[e] ----------------
// A: Hact rows [MT][KT] fp16 (contiguous), B: w2h[e] [F][H] = [k][n] row-major
__global__ __launch_bounds__(256, 2) void k_gemm2() {
    extern __shared__ char smem[];

    int e = blockIdx.z;
    int ne = g_cnt[e];
    int gm = blockIdx.y * MT;
    if (gm >= ne) return;
    int gn = blockIdx.x * NT;

    int tid = threadIdx.x, lane = tid & 31, wid = tid >> 5;
    int wm = wid & 1, wn = wid >> 1;

    const __half* aSrc = g_Hact + ((size_t)e * T + gm) * F;
    const __half* wB = g_w2h + (size_t)e * F * H;
    uint32_t sbase = smem_u32(smem);

    float cfrag[4][4][4];
#pragma unroll
    for (int i = 0; i < 4; i++)
#pragma unroll
        for (int j = 0; j < 4; j++)
#pragma unroll
            for (int k = 0; k < 4; k++) cfrag[i][j][k] = 0.0f;

    const int k_iters = F / KT;  // 64

    auto load_stage = [&](int buf, int k0) {
        uint32_t aB = sbase + buf * STAGE_BYTES;
        uint32_t bB = aB + A_STAGE_BYTES;
#pragma unroll
        for (int q = 0; q < 2; q++) {
            int g = tid + q * 256;
            int r = g >> 2, cg = g & 3;
            const __half* src = aSrc + (size_t)r * F + k0 + cg * 8;
            cp_async16(aB + r * (A_STRIDE * 2) + cg * 16, src, 16u);
        }
#pragma unroll
        for (int q = 0; q < 2; q++) {
            int g = tid + q * 256;
            int r = g >> 4, cg = g & 15;
            const __half* src = wB + (size_t)(k0 + r) * H + gn + cg * 8;
            cp_async16(bB + r * (B_STRIDE * 2) + cg * 16, src, 16u);
        }
    };

    load_stage(0, 0); CP_COMMIT();
    load_stage(1, KT); CP_COMMIT();

    for (int it = 0; it < k_iters; it++) {
        CP_WAIT1();
        __syncthreads();
        if (it + 2 < k_iters) load_stage((it + 2) % NSTG, (it + 2) * KT);
        CP_COMMIT();

        uint32_t aS = sbase + (it % NSTG) * STAGE_BYTES;
        uint32_t bS = aS + A_STAGE_BYTES;
#pragma unroll
        for (int ks = 0; ks < 2; ks++) {
            uint32_t a[4][4], b[2][4];
#pragma unroll
            for (int mf = 0; mf < 4; mf++) {
                int m = wm * 64 + mf * 16 + (lane & 15);
                int k = ks * 16 + (lane >> 4) * 8;
                ldsm_x4(a[mf][0], a[mf][1], a[mf][2], a[mf][3],
                        aS + m * (A_STRIDE * 2) + k * 2);
            }
#pragma unroll
            for (int np = 0; np < 2; np++) {
                int k = ks * 16 + (lane & 7) + ((lane >> 3) & 1) * 8;
                int n = wn * 32 + np * 16 + (lane >> 4) * 8;
                ldsm_x4_t(b[np][0], b[np][1], b[np][2], b[np][3],
                          bS + k * (B_STRIDE * 2) + n * 2);
            }
#pragma unroll
            for (int mf = 0; mf < 4; mf++)
#pragma unroll
                for (int nf = 0; nf < 4; nf++)
                    mma_f16(cfrag[mf][nf], a[mf],
                            b[nf >> 1][(nf & 1) * 2], b[nf >> 1][(nf & 1) * 2 + 1]);
        }
    }
    CP_WAIT0();

#pragma unroll
    for (int nf = 0; nf < 4; nf++) {
        int col = gn + wn * 32 + nf * 8 + (lane & 3) * 2;
#pragma unroll
        for (int mf = 0; mf < 4; mf++) {
            int r0 = gm + wm * 64 + mf * 16 + (lane >> 2);
            float* c = cfrag[mf][nf];
            if (r0 < ne) {
                float* o = g_Yout + ((size_t)e * T + r0) * H + col;
                o[0] = c[0]; o[1] = c[1];
            }
            if (r0 + 8 < ne) {
                float* o = g_Yout + ((size_t)e * T + r0 + 8) * H + col;
                o[0] = c[2]; o[1] = c[3];
            }
        }
    }
}

// ---------------- combine ----------------
__global__ void k_combine(const float* __restrict__ b2,
                          float* __restrict__ out) {
    int t = blockIdx.x;
    int p0 = g_pair[2 * t], p1 = g_pair[2 * t + 1];
    int e0 = g_pexp[2 * t], e1 = g_pexp[2 * t + 1];

    const float4* y0 = (const float4*)(g_Yout + (size_t)p0 * H);
    const float4* y1 = (const float4*)(g_Yout + (size_t)p1 * H);
    const float4* bb0 = (const float4*)(b2 + (size_t)e0 * H);
    const float4* bb1 = (const float4*)(b2 + (size_t)e1 * H);
    float4* o = (float4*)(out + (size_t)t * H);

    int i = threadIdx.x;
    float4 a = y0[i], b = y1[i], c = bb0[i], d = bb1[i];
    o[i] = make_float4(a.x + b.x + c.x + d.x,
                       a.y + b.y + c.y + d.y,
                       a.z + b.z + c.z + d.z,
                       a.w + b.w + c.w + d.w);
}

// ---------------- finalize ----------------
__global__ void k_finalize(float* __restrict__ out, int out_size) {
    if (out_size > T * H) {
        float aux = g_loss[0] * (0.001f / (float)BATCH);
        float z   = g_loss[1] * (0.001f / (float)(T * E));
        out[T * H] = aux + z;
    }
}

extern "C" void kernel_launch(void* const* d_in, const int* in_sizes, int n_in,
                              void* d_out, int out_size) {
    const float* x  = (const float*)d_in[0];
    const float* rw = (const float*)d_in[1];
    const float* w1 = (const float*)d_in[2];
    const float* b1 = (const float*)d_in[3];
    const float* w2 = (const float*)d_in[4];
    const float* b2 = (const float*)d_in[5];
    float* out = (float*)d_out;

    cudaFuncSetAttribute(k_gemm1, cudaFuncAttributeMaxDynamicSharedMemorySize, SMEM_DYN);
    cudaFuncSetAttribute(k_gemm2, cudaFuncAttributeMaxDynamicSharedMemorySize, SMEM_DYN);

    __half *xh, *w1h, *w2h;
    cudaGetSymbolAddress((void**)&xh, g_xh);
    cudaGetSymbolAddress((void**)&w1h, g_w1h);
    cudaGetSymbolAddress((void**)&w2h, g_w2h);

    k_init<<<1, 32>>>();
    k_router<<<T / 8, 256>>>(x, rw);

    k_cvt<<<(T * H / 4 + 255) / 256, 256>>>((const float4*)x, (__half2*)xh, T * H / 4);
    k_cvt<<<(E * H * F / 4 + 255) / 256, 256>>>((const float4*)w1, (__half2*)w1h, E * H * F / 4);
    k_cvt<<<(E * F * H / 4 + 255) / 256, 256>>>((const float4*)w2, (__half2*)w2h, E * F * H / 4);

    k_gemm1<<<dim3(F / NT, T / MT, E), 256, SMEM_DYN>>>(b1);
    k_gemm2<<<dim3(H / NT, T / MT, E), 256, SMEM_DYN>>>();

    k_combine<<<T, 256>>>(b2, out);
    k_finalize<<<1, 1>>>(out, out_size);
}